// round 14
// baseline (speedup 1.0000x reference)
#include <cuda_runtime.h>
#include <cuda_bf16.h>
#include <math.h>
#include <stdint.h>

// LSTM scan: B=256, T=512, D=1, H=512. W:[513,2048] (i,j,f,o). out fp32 [B,T,H].
// bf16 HMMA, fp32 via 3-term split: ahi*whi + ahi*wlo + alo*whi.
// Round 14: round-13 core + fine-grained dataflow sync done right:
//   per-(mb,chunk) producer counters, tid-0-only acquire spins folded into the
//   existing per-iter __syncthreads; arrive moved before the streaming out stores.

#define BATCH 256
#define TSTEPS 512
#define HDIM 512
#define GDIM 2048
#define A_OFF     131072            // W: 16 tiles x 8KB, then A ring 4 x 16KB
#define SMEM_DYN  196608
#define ZPITCH 66

__device__ __align__(16) __nv_bfloat16 g_Wp[GDIM * 1024];     // [p][whi(512)|wlo(512)]
__device__ __align__(16) __nv_bfloat16 g_A[2][BATCH * 1024];  // [b][hi(512)|lo(512)]
__device__ unsigned int g_bar2[4][8];   // [mb][chunk], 4 producers each

__device__ __forceinline__ uint32_t cvta_s(const void* p) {
    return (uint32_t)__cvta_generic_to_shared(p);
}
__device__ __forceinline__ void cp16(uint32_t dst, const void* src) {
    asm volatile("cp.async.cg.shared.global [%0], [%1], 16;" :: "r"(dst), "l"(src));
}
#define CP_COMMIT() asm volatile("cp.async.commit_group;")
#define CP_WAIT2()  asm volatile("cp.async.wait_group 2;")
#define CP_WAIT0()  asm volatile("cp.async.wait_group 0;")

#define LDSM_X4(r0, r1, r2, r3, a)                                             \
    asm volatile("ldmatrix.sync.aligned.m8n8.x4.shared.b16 {%0,%1,%2,%3}, [%4];" \
                 : "=r"(r0), "=r"(r1), "=r"(r2), "=r"(r3) : "r"(a))

#define MMA16816(c, a0, a1, a2, a3, b0, b1)                                    \
    asm volatile("mma.sync.aligned.m16n8k16.row.col.f32.bf16.bf16.f32 "        \
                 "{%0,%1,%2,%3}, {%4,%5,%6,%7}, {%8,%9}, {%0,%1,%2,%3};"       \
                 : "+f"((c)[0]), "+f"((c)[1]), "+f"((c)[2]), "+f"((c)[3])      \
                 : "r"(a0), "r"(a1), "r"(a2), "r"(a3), "r"(b0), "r"(b1))

#define MMA_PASS(A, B)                                                          \
    _Pragma("unroll")                                                           \
    for (int kk = 0; kk < 2; kk++) {                                            \
        const uint32_t* a = (A) + kk * 8;                                       \
        const uint32_t* b = (B) + kk * 8;                                       \
        MMA16816(acc[0][0], a[0], a[1], a[2], a[3], b[0], b[1]);                \
        MMA16816(acc[0][1], a[0], a[1], a[2], a[3], b[2], b[3]);                \
        MMA16816(acc[0][2], a[0], a[1], a[2], a[3], b[4], b[5]);                \
        MMA16816(acc[0][3], a[0], a[1], a[2], a[3], b[6], b[7]);                \
        MMA16816(acc[1][0], a[4], a[5], a[6], a[7], b[0], b[1]);                \
        MMA16816(acc[1][1], a[4], a[5], a[6], a[7], b[2], b[3]);                \
        MMA16816(acc[1][2], a[4], a[5], a[6], a[7], b[4], b[5]);                \
        MMA16816(acc[1][3], a[4], a[5], a[6], a[7], b[6], b[7]);                \
    }

__device__ __forceinline__ float sigmoidf_(float v) {
    return 1.0f / (1.0f + expf(-v));
}
// single-thread acquire spin
__device__ __forceinline__ void wait_cnt(const unsigned int* p, unsigned int target) {
    unsigned int v;
    do {
        asm volatile("ld.acquire.gpu.global.u32 %0, [%1];" : "=r"(v) : "l"(p) : "memory");
    } while (v < target);
}

// W'[p][k]: p = h*4+g -> gcol = g*512+h; k<512: Whi(k), k>=512: Wlo(k-512).
__global__ void conv_w(const float* __restrict__ W) {
    int idx = blockIdx.x * blockDim.x + threadIdx.x;
    if (idx >= GDIM * 1024) return;
    int p = idx >> 10;
    int k = idx & 1023;
    int g = p & 3, h = p >> 2;
    int kk = k & 511;
    float w = W[(size_t)(kk + 1) * GDIM + g * HDIM + h];
    __nv_bfloat16 hi = __float2bfloat16(w);
    g_Wp[idx] = (k >= 512) ? __float2bfloat16(w - __bfloat162float(hi)) : hi;
}

__global__ void lstm_init() {
    int i = blockIdx.x * blockDim.x + threadIdx.x;
    if (i < BATCH * 1024) {
        g_A[0][i] = __float2bfloat16(0.0f);
        g_A[1][i] = __float2bfloat16(0.0f);
    }
    if (i < 32) ((unsigned int*)g_bar2)[i] = 0u;
}

// grid (32 nb, 4 mb) = 128 CTAs, 256 threads (8 warps), persistent over t.
__global__ void __launch_bounds__(256, 1) lstm_persist(
    const float* __restrict__ x,
    const float* __restrict__ W,
    const float* __restrict__ bias,
    float* __restrict__ out)
{
    extern __shared__ __align__(128) char dsmem[];
    __shared__ float s_w0[64], s_b[64];

    const int tid = threadIdx.x;
    const int wid = tid >> 5;
    const int lane = tid & 31;
    const int nb = blockIdx.x;
    const int mb = blockIdx.y;
    const int m_base = mb * 64;

    const uint32_t sbase = cvta_s(dsmem);
    const uint32_t abase = sbase + A_OFF;
    float* z0 = (float*)(dsmem + A_OFF);
    float* z1 = z0 + 64 * ZPITCH;

    const int ks = wid >> 2;
    const int w2 = wid & 3;
    const int warp_m = (w2 >> 1) * 32;
    const int warp_n = (w2 & 1) * 32;

    if (tid < 64) {
        int gcol = (tid & 3) * HDIM + nb * 16 + (tid >> 2);
        s_w0[tid] = W[gcol];
        s_b[tid] = bias[gcol];
    }

    const int lr = tid >> 3;
    const int lc16 = tid & 7;
    const uint32_t so0 = (uint32_t)(lr * 128 + ((lc16 ^ (lr & 7)) * 16));
    const uint32_t so1 = (uint32_t)((lr + 32) * 128 + ((lc16 ^ (lr & 7)) * 16));

    // ---- preload W slice into smem: 16 tiles (whi 0-7, wlo 8-15) ----
    #pragma unroll 1
    for (int j = 0; j < 16; j++) {
        int wo = ((j >= 8) ? 512 : 0) + (j & 7) * 64;
        cp16(sbase + j * 8192 + so0,
             &g_Wp[(size_t)(nb * 64 + lr) * 1024 + wo + lc16 * 8]);
        cp16(sbase + j * 8192 + so1,
             &g_Wp[(size_t)(nb * 64 + lr + 32) * 1024 + wo + lc16 * 8]);
    }
    CP_COMMIT();
    CP_WAIT0();
    __syncthreads();

    // ---- LDSM addressing ----
    const uint32_t a_row = warp_m + (lane & 15);
    const uint32_t b_row = warp_n + (lane & 7) + ((lane >> 4) << 3);
    const uint32_t a_sw = a_row & 7, b_sw = b_row & 7;
    const uint32_t a_c16base = ks * 4 + (lane >> 4);
    const uint32_t b_c16base = ks * 4 + ((lane >> 3) & 1);

    // ---- per-thread persistent cell state ----
    float creg[4] = {0.0f, 0.0f, 0.0f, 0.0f};

    #pragma unroll 1
    for (int t = 0; t < TSTEPS; t++) {
        const __nv_bfloat16* __restrict__ Ain = g_A[t & 1];
        __nv_bfloat16* __restrict__ Aout = g_A[(t + 1) & 1];
        const unsigned int bar_target = 4u * (unsigned)t;

        // preload x for this step (independent of h)
        float xv[4];
        #pragma unroll
        for (int i = 0; i < 4; i++) {
            int b_row = m_base + ((i * 256 + tid) >> 4);
            xv[i] = x[b_row * TSTEPS + t];
        }

        auto prefA = [&](int i) {
            uint32_t ab = abase + (i & 3) * 16384;
            const __nv_bfloat16* s0 = &Ain[(size_t)(m_base + lr) * 1024 + i * 64 + lc16 * 8];
            const __nv_bfloat16* s1 = &Ain[(size_t)(m_base + lr + 32) * 1024 + i * 64 + lc16 * 8];
            cp16(ab + so0, s0);
            cp16(ab + so1, s1);
            cp16(ab + 8192 + so0, s0 + 512);
            cp16(ab + 8192 + so1, s1 + 512);
        };

        float acc[2][4][4] = {};

        // tid-0 waits producers of chunks 0-2 (no-op at t=0), everyone else parks
        if (tid == 0 && t > 0) {
            wait_cnt(&g_bar2[mb][0], bar_target);
            wait_cnt(&g_bar2[mb][1], bar_target);
            wait_cnt(&g_bar2[mb][2], bar_target);
        }
        __syncthreads();

        prefA(0); CP_COMMIT();
        prefA(1); CP_COMMIT();
        prefA(2); CP_COMMIT();

        #pragma unroll 1
        for (int i = 0; i < 8; i++) {
            // W fragments: static smem tiles, overlap in-flight cp.async
            uint32_t bh[16], bl[16];
            const uint32_t whb = sbase + i * 8192;
            const uint32_t wlb = sbase + (8 + i) * 8192;
            #pragma unroll
            for (int kk = 0; kk < 2; kk++) {
                uint32_t c16b = ((b_c16base + kk * 2) ^ b_sw) * 16;
                uint32_t baddr = whb + b_row * 128 + c16b;
                LDSM_X4(bh[kk*8+0], bh[kk*8+1], bh[kk*8+2], bh[kk*8+3], baddr);
                LDSM_X4(bh[kk*8+4], bh[kk*8+5], bh[kk*8+6], bh[kk*8+7], baddr + 16 * 128);
                uint32_t baddr2 = wlb + b_row * 128 + c16b;
                LDSM_X4(bl[kk*8+0], bl[kk*8+1], bl[kk*8+2], bl[kk*8+3], baddr2);
                LDSM_X4(bl[kk*8+4], bl[kk*8+5], bl[kk*8+6], bl[kk*8+7], baddr2 + 16 * 128);
            }

            CP_WAIT2();          // my groups 0..i done => my share of chunk i landed
            // tid-0 waits the producers of the chunk we are about to prefetch
            if (tid == 0 && t > 0 && i + 3 < 8)
                wait_cnt(&g_bar2[mb][i + 3], bar_target);
            __syncthreads();     // publish chunk i; iter i-1 readers done; wait visible

            if (i + 3 < 8) prefA(i + 3);
            CP_COMMIT();

            uint32_t ah[16], al[16];
            const uint32_t ab = abase + (i & 3) * 16384;
            #pragma unroll
            for (int kk = 0; kk < 2; kk++) {
                uint32_t c16a = ((a_c16base + kk * 2) ^ a_sw) * 16;
                uint32_t aaddr = ab + a_row * 128 + c16a;
                LDSM_X4(ah[kk*8+0], ah[kk*8+1], ah[kk*8+2], ah[kk*8+3], aaddr);
                LDSM_X4(ah[kk*8+4], ah[kk*8+5], ah[kk*8+6], ah[kk*8+7], aaddr + 16 * 128);
                uint32_t aaddr2 = ab + 8192 + a_row * 128 + c16a;
                LDSM_X4(al[kk*8+0], al[kk*8+1], al[kk*8+2], al[kk*8+3], aaddr2);
                LDSM_X4(al[kk*8+4], al[kk*8+5], al[kk*8+6], al[kk*8+7], aaddr2 + 16 * 128);
            }

            MMA_PASS(ah, bh);    // a_hi * w_hi
            MMA_PASS(ah, bl);    // a_hi * w_lo
            MMA_PASS(al, bh);    // a_lo * w_hi
        }

        // ---- z stage (slots 0-2 alias; iter-7 stragglers touch only slot 3) ----
        float* zw = ks ? z1 : z0;
        #pragma unroll
        for (int mf = 0; mf < 2; mf++)
            #pragma unroll
            for (int nf = 0; nf < 4; nf++) {
                int row = warp_m + mf * 16 + (lane >> 2);
                int col = warp_n + nf * 8 + (lane & 3) * 2;
                *(float2*)&zw[row * ZPITCH + col] =
                    make_float2(acc[mf][nf][0], acc[mf][nf][1]);
                *(float2*)&zw[(row + 8) * ZPITCH + col] =
                    make_float2(acc[mf][nf][2], acc[mf][nf][3]);
            }
        __syncthreads();

        // ---- gate fusion: compute + Aout stores; out stores deferred ----
        float hnv[4];
        int orow[4], ocol[4];
        #pragma unroll
        for (int i = 0; i < 4; i++) {
            int o = i * 256 + tid;
            int r = o >> 4;
            int h = o & 15;
            int b_row = m_base + r;
            int h_col = nb * 16 + h;
            orow[i] = b_row; ocol[i] = h_col;

            const float* za = &z0[r * ZPITCH + h * 4];
            const float* zb = &z1[r * ZPITCH + h * 4];

            float zi = za[0] + zb[0] + fmaf(xv[i], s_w0[h * 4 + 0], s_b[h * 4 + 0]);
            float zj = za[1] + zb[1] + fmaf(xv[i], s_w0[h * 4 + 1], s_b[h * 4 + 1]);
            float zf = za[2] + zb[2] + fmaf(xv[i], s_w0[h * 4 + 2], s_b[h * 4 + 2]);
            float zo = za[3] + zb[3] + fmaf(xv[i], s_w0[h * 4 + 3], s_b[h * 4 + 3]);

            float fg = sigmoidf_(zf + 1.0f);
            float ig = sigmoidf_(zi);
            float og = sigmoidf_(zo);
            float cn = creg[i] * fg + ig * tanhf(zj);
            float hn = tanhf(cn) * og;
            creg[i] = cn;
            hnv[i] = hn;

            __nv_bfloat16 hi = __float2bfloat16(hn);
            __nv_bfloat16 lo = __float2bfloat16(hn - __bfloat162float(hi));
            Aout[(size_t)b_row * 1024 + h_col] = hi;
            Aout[(size_t)b_row * 1024 + 512 + h_col] = lo;
        }

        // ---- arrive early (before out stores): release consumers ----
        __syncthreads();             // Aout stores + z reads complete CTA-wide
        if (t < TSTEPS - 1 && tid == 0) {
            __threadfence();
            asm volatile("red.release.gpu.global.add.u32 [%0], %1;"
                         :: "l"(&g_bar2[mb][nb >> 2]), "r"(1u) : "memory");
        }

        // ---- streaming out stores (write-once, bypass L2 residency) ----
        #pragma unroll
        for (int i = 0; i < 4; i++) {
            __stcs(&out[(size_t)orow[i] * (TSTEPS * HDIM) + (size_t)t * HDIM + ocol[i]],
                   hnv[i]);
        }
    }
}

extern "C" void kernel_launch(void* const* d_in, const int* in_sizes, int n_in,
                              void* d_out, int out_size) {
    const float* x    = (const float*)d_in[0];
    const float* W    = (const float*)d_in[1];
    const float* bias = (const float*)d_in[2];
    float* out = (float*)d_out;
    (void)in_sizes; (void)n_in; (void)out_size;

    cudaFuncSetAttribute(lstm_persist,
                         cudaFuncAttributeMaxDynamicSharedMemorySize, SMEM_DYN);

    conv_w<<<(GDIM * 1024 + 255) / 256, 256>>>(W);
    lstm_init<<<(BATCH * 1024 + 255) / 256, 256>>>();

    dim3 grid(32, 4);   // 128 CTAs, 1/SM, all co-resident
    lstm_persist<<<grid, 256, SMEM_DYN>>>(x, W, bias, out);
}

// round 15
// speedup vs baseline: 1.1941x; 1.1941x over previous
#include <cuda_runtime.h>
#include <cuda_bf16.h>
#include <math.h>
#include <stdint.h>

// LSTM scan: B=256, T=512, D=1, H=512. W:[513,2048] (i,j,f,o). out fp32 [B,T,H].
// bf16 HMMA, fp32 via 3-term split: ahi*whi + ahi*wlo + alo*whi.
// Round 15: round-13 core (monolithic per-mb barrier) +
//   KC=128 mainloop (4 iters x 2 sub-phases), tid-0-only fence,
//   arrive-before-streaming-out-stores.

#define BATCH 256
#define TSTEPS 512
#define HDIM 512
#define GDIM 2048
#define A_OFF     131072            // W: 16 tiles x 8KB, then A ring 2 x 32KB
#define SMEM_DYN  196608
#define ZPITCH 66

__device__ __align__(16) __nv_bfloat16 g_Wp[GDIM * 1024];     // [p][whi(512)|wlo(512)]
__device__ __align__(16) __nv_bfloat16 g_A[2][BATCH * 1024];  // [b][hi(512)|lo(512)]
__device__ unsigned int g_bar[4];

__device__ __forceinline__ uint32_t cvta_s(const void* p) {
    return (uint32_t)__cvta_generic_to_shared(p);
}
__device__ __forceinline__ void cp16(uint32_t dst, const void* src) {
    asm volatile("cp.async.cg.shared.global [%0], [%1], 16;" :: "r"(dst), "l"(src));
}
#define CP_COMMIT() asm volatile("cp.async.commit_group;")
#define CP_WAIT0()  asm volatile("cp.async.wait_group 0;")

#define LDSM_X4(r0, r1, r2, r3, a)                                             \
    asm volatile("ldmatrix.sync.aligned.m8n8.x4.shared.b16 {%0,%1,%2,%3}, [%4];" \
                 : "=r"(r0), "=r"(r1), "=r"(r2), "=r"(r3) : "r"(a))

#define MMA16816(c, a0, a1, a2, a3, b0, b1)                                    \
    asm volatile("mma.sync.aligned.m16n8k16.row.col.f32.bf16.bf16.f32 "        \
                 "{%0,%1,%2,%3}, {%4,%5,%6,%7}, {%8,%9}, {%0,%1,%2,%3};"       \
                 : "+f"((c)[0]), "+f"((c)[1]), "+f"((c)[2]), "+f"((c)[3])      \
                 : "r"(a0), "r"(a1), "r"(a2), "r"(a3), "r"(b0), "r"(b1))

#define MMA_PASS(A, B)                                                          \
    _Pragma("unroll")                                                           \
    for (int kk = 0; kk < 2; kk++) {                                            \
        const uint32_t* a = (A) + kk * 8;                                       \
        const uint32_t* b = (B) + kk * 8;                                       \
        MMA16816(acc[0][0], a[0], a[1], a[2], a[3], b[0], b[1]);                \
        MMA16816(acc[0][1], a[0], a[1], a[2], a[3], b[2], b[3]);                \
        MMA16816(acc[0][2], a[0], a[1], a[2], a[3], b[4], b[5]);                \
        MMA16816(acc[0][3], a[0], a[1], a[2], a[3], b[6], b[7]);                \
        MMA16816(acc[1][0], a[4], a[5], a[6], a[7], b[0], b[1]);                \
        MMA16816(acc[1][1], a[4], a[5], a[6], a[7], b[2], b[3]);                \
        MMA16816(acc[1][2], a[4], a[5], a[6], a[7], b[4], b[5]);                \
        MMA16816(acc[1][3], a[4], a[5], a[6], a[7], b[6], b[7]);                \
    }

__device__ __forceinline__ float sigmoidf_(float v) {
    return 1.0f / (1.0f + expf(-v));
}

// W'[p][k]: p = h*4+g -> gcol = g*512+h; k<512: Whi(k), k>=512: Wlo(k-512).
__global__ void conv_w(const float* __restrict__ W) {
    int idx = blockIdx.x * blockDim.x + threadIdx.x;
    if (idx >= GDIM * 1024) return;
    int p = idx >> 10;
    int k = idx & 1023;
    int g = p & 3, h = p >> 2;
    int kk = k & 511;
    float w = W[(size_t)(kk + 1) * GDIM + g * HDIM + h];
    __nv_bfloat16 hi = __float2bfloat16(w);
    g_Wp[idx] = (k >= 512) ? __float2bfloat16(w - __bfloat162float(hi)) : hi;
}

__global__ void lstm_init() {
    int i = blockIdx.x * blockDim.x + threadIdx.x;
    if (i < BATCH * 1024) {
        g_A[0][i] = __float2bfloat16(0.0f);
        g_A[1][i] = __float2bfloat16(0.0f);
    }
    if (i < 4) g_bar[i] = 0u;
}

// grid (32 nb, 4 mb) = 128 CTAs, 256 threads (8 warps), persistent over t.
__global__ void __launch_bounds__(256, 1) lstm_persist(
    const float* __restrict__ x,
    const float* __restrict__ W,
    const float* __restrict__ bias,
    float* __restrict__ out)
{
    extern __shared__ __align__(128) char dsmem[];
    __shared__ float s_w0[64], s_b[64];

    const int tid = threadIdx.x;
    const int wid = tid >> 5;
    const int lane = tid & 31;
    const int nb = blockIdx.x;
    const int mb = blockIdx.y;
    const int m_base = mb * 64;

    const uint32_t sbase = cvta_s(dsmem);
    const uint32_t abase = sbase + A_OFF;
    float* z0 = (float*)(dsmem + A_OFF);
    float* z1 = z0 + 64 * ZPITCH;

    const int ks = wid >> 2;
    const int w2 = wid & 3;
    const int warp_m = (w2 >> 1) * 32;
    const int warp_n = (w2 & 1) * 32;

    if (tid < 64) {
        int gcol = (tid & 3) * HDIM + nb * 16 + (tid >> 2);
        s_w0[tid] = W[gcol];
        s_b[tid] = bias[gcol];
    }

    const int lr = tid >> 3;
    const int lc16 = tid & 7;
    const uint32_t so0 = (uint32_t)(lr * 128 + ((lc16 ^ (lr & 7)) * 16));
    const uint32_t so1 = (uint32_t)((lr + 32) * 128 + ((lc16 ^ (lr & 7)) * 16));

    // ---- preload W slice into smem: 16 tiles (whi 0-7, wlo 8-15) ----
    #pragma unroll 1
    for (int j = 0; j < 16; j++) {
        int wo = ((j >= 8) ? 512 : 0) + (j & 7) * 64;
        cp16(sbase + j * 8192 + so0,
             &g_Wp[(size_t)(nb * 64 + lr) * 1024 + wo + lc16 * 8]);
        cp16(sbase + j * 8192 + so1,
             &g_Wp[(size_t)(nb * 64 + lr + 32) * 1024 + wo + lc16 * 8]);
    }
    CP_COMMIT();
    CP_WAIT0();
    __syncthreads();

    // ---- LDSM addressing ----
    const uint32_t a_row = warp_m + (lane & 15);
    const uint32_t b_row = warp_n + (lane & 7) + ((lane >> 4) << 3);
    const uint32_t a_sw = a_row & 7, b_sw = b_row & 7;
    const uint32_t a_c16base = ks * 4 + (lane >> 4);
    const uint32_t b_c16base = ks * 4 + ((lane >> 3) & 1);

    // ---- per-thread persistent cell state ----
    float creg[4] = {0.0f, 0.0f, 0.0f, 0.0f};

    #pragma unroll 1
    for (int t = 0; t < TSTEPS; t++) {
        const __nv_bfloat16* __restrict__ Ain = g_A[t & 1];
        __nv_bfloat16* __restrict__ Aout = g_A[(t + 1) & 1];

        // preload x for this step (independent of h; hides behind the GEMM)
        float xv[4];
        #pragma unroll
        for (int i = 0; i < 4; i++) {
            int b_row = m_base + ((i * 256 + tid) >> 4);
            xv[i] = x[b_row * TSTEPS + t];
        }

        // chunk i covers k in [128i, 128i+128): slot = 4 subtiles of 8KB
        // [hi_sub0 | hi_sub1 | lo_sub0 | lo_sub1]
        auto prefA = [&](int i) {
            uint32_t ab = abase + (i & 1) * 32768;
            const __nv_bfloat16* s0 = &Ain[(size_t)(m_base + lr) * 1024 + i * 128 + lc16 * 8];
            const __nv_bfloat16* s1 = &Ain[(size_t)(m_base + lr + 32) * 1024 + i * 128 + lc16 * 8];
            cp16(ab + so0, s0);                  // hi sub0
            cp16(ab + so1, s1);
            cp16(ab + 8192 + so0, s0 + 64);      // hi sub1
            cp16(ab + 8192 + so1, s1 + 64);
            cp16(ab + 16384 + so0, s0 + 512);    // lo sub0
            cp16(ab + 16384 + so1, s1 + 512);
            cp16(ab + 24576 + so0, s0 + 576);    // lo sub1
            cp16(ab + 24576 + so1, s1 + 576);
        };

        float acc[2][4][4] = {};

        prefA(0); CP_COMMIT();

        #pragma unroll 1
        for (int i = 0; i < 4; i++) {
            CP_WAIT0();          // my share of chunk i landed (<=1 group in flight)
            __syncthreads();     // publish chunk i; iter i-1 readers done
            if (i + 1 < 4) prefA(i + 1);   // slot (i+1)&1: readers were iter i-1
            CP_COMMIT();

            const uint32_t ab = abase + (i & 1) * 32768;
            #pragma unroll
            for (int sub = 0; sub < 2; sub++) {
                // W fragments for 64k-subchunk (2i+sub)
                uint32_t bh[16], bl[16];
                const uint32_t whb = sbase + (2 * i + sub) * 8192;
                const uint32_t wlb = sbase + (8 + 2 * i + sub) * 8192;
                #pragma unroll
                for (int kk = 0; kk < 2; kk++) {
                    uint32_t c16b = ((b_c16base + kk * 2) ^ b_sw) * 16;
                    uint32_t baddr = whb + b_row * 128 + c16b;
                    LDSM_X4(bh[kk*8+0], bh[kk*8+1], bh[kk*8+2], bh[kk*8+3], baddr);
                    LDSM_X4(bh[kk*8+4], bh[kk*8+5], bh[kk*8+6], bh[kk*8+7], baddr + 16 * 128);
                    uint32_t baddr2 = wlb + b_row * 128 + c16b;
                    LDSM_X4(bl[kk*8+0], bl[kk*8+1], bl[kk*8+2], bl[kk*8+3], baddr2);
                    LDSM_X4(bl[kk*8+4], bl[kk*8+5], bl[kk*8+6], bl[kk*8+7], baddr2 + 16 * 128);
                }

                uint32_t ah[16], al[16];
                const uint32_t ahb = ab + sub * 8192;           // hi subtile
                const uint32_t alb = ab + 16384 + sub * 8192;   // lo subtile
                #pragma unroll
                for (int kk = 0; kk < 2; kk++) {
                    uint32_t c16a = ((a_c16base + kk * 2) ^ a_sw) * 16;
                    uint32_t aaddr = ahb + a_row * 128 + c16a;
                    LDSM_X4(ah[kk*8+0], ah[kk*8+1], ah[kk*8+2], ah[kk*8+3], aaddr);
                    LDSM_X4(ah[kk*8+4], ah[kk*8+5], ah[kk*8+6], ah[kk*8+7], aaddr + 16 * 128);
                    uint32_t aaddr2 = alb + a_row * 128 + c16a;
                    LDSM_X4(al[kk*8+0], al[kk*8+1], al[kk*8+2], al[kk*8+3], aaddr2);
                    LDSM_X4(al[kk*8+4], al[kk*8+5], al[kk*8+6], al[kk*8+7], aaddr2 + 16 * 128);
                }

                MMA_PASS(ah, bh);    // a_hi * w_hi
                MMA_PASS(ah, bl);    // a_hi * w_lo
                MMA_PASS(al, bh);    // a_lo * w_hi
            }
        }
        __syncthreads();     // z aliases slot 0 + head of slot 1 (iter-3 readers)

        // ---- z stage (dual accumulators per k-split) ----
        float* zw = ks ? z1 : z0;
        #pragma unroll
        for (int mf = 0; mf < 2; mf++)
            #pragma unroll
            for (int nf = 0; nf < 4; nf++) {
                int row = warp_m + mf * 16 + (lane >> 2);
                int col = warp_n + nf * 8 + (lane & 3) * 2;
                *(float2*)&zw[row * ZPITCH + col] =
                    make_float2(acc[mf][nf][0], acc[mf][nf][1]);
                *(float2*)&zw[(row + 8) * ZPITCH + col] =
                    make_float2(acc[mf][nf][2], acc[mf][nf][3]);
            }
        __syncthreads();

        // ---- gate fusion: compute + Aout stores; out stores deferred ----
        float hnv[4];
        int orow[4], ocol[4];
        #pragma unroll
        for (int i = 0; i < 4; i++) {
            int o = i * 256 + tid;
            int r = o >> 4;
            int h = o & 15;
            int b_row = m_base + r;
            int h_col = nb * 16 + h;
            orow[i] = b_row; ocol[i] = h_col;

            const float* za = &z0[r * ZPITCH + h * 4];
            const float* zb = &z1[r * ZPITCH + h * 4];

            float zi = za[0] + zb[0] + fmaf(xv[i], s_w0[h * 4 + 0], s_b[h * 4 + 0]);
            float zj = za[1] + zb[1] + fmaf(xv[i], s_w0[h * 4 + 1], s_b[h * 4 + 1]);
            float zf = za[2] + zb[2] + fmaf(xv[i], s_w0[h * 4 + 2], s_b[h * 4 + 2]);
            float zo = za[3] + zb[3] + fmaf(xv[i], s_w0[h * 4 + 3], s_b[h * 4 + 3]);

            float fg = sigmoidf_(zf + 1.0f);
            float ig = sigmoidf_(zi);
            float og = sigmoidf_(zo);
            float cn = creg[i] * fg + ig * tanhf(zj);
            float hn = tanhf(cn) * og;
            creg[i] = cn;
            hnv[i] = hn;

            __nv_bfloat16 hi = __float2bfloat16(hn);
            __nv_bfloat16 lo = __float2bfloat16(hn - __bfloat162float(hi));
            Aout[(size_t)b_row * 1024 + h_col] = hi;
            Aout[(size_t)b_row * 1024 + 512 + h_col] = lo;
        }

        // ---- arrive early: Aout published, then overlap out stores ----
        const int last = (t == TSTEPS - 1);
        if (!last) {
            __syncthreads();              // all threads' Aout stores done
            if (tid == 0) {
                __threadfence();          // tid-0 only: release Aout gpu-wide
                asm volatile("red.release.gpu.global.add.u32 [%0], %1;"
                             :: "l"(&g_bar[mb]), "r"(1u) : "memory");
            }
        }

        // ---- streaming out stores (write-once), overlap other CTAs' work ----
        #pragma unroll
        for (int i = 0; i < 4; i++) {
            __stcs(&out[(size_t)orow[i] * (TSTEPS * HDIM) + (size_t)t * HDIM + ocol[i]],
                   hnv[i]);
        }

        if (!last) {
            if (tid == 0) {
                unsigned int target = 32u * (unsigned)(t + 1);
                unsigned int v;
                do {
                    asm volatile("ld.acquire.gpu.global.u32 %0, [%1];"
                                 : "=r"(v) : "l"(&g_bar[mb]) : "memory");
                } while (v < target);
            }
            __syncthreads();
        }
    }
}

extern "C" void kernel_launch(void* const* d_in, const int* in_sizes, int n_in,
                              void* d_out, int out_size) {
    const float* x    = (const float*)d_in[0];
    const float* W    = (const float*)d_in[1];
    const float* bias = (const float*)d_in[2];
    float* out = (float*)d_out;
    (void)in_sizes; (void)n_in; (void)out_size;

    cudaFuncSetAttribute(lstm_persist,
                         cudaFuncAttributeMaxDynamicSharedMemorySize, SMEM_DYN);

    conv_w<<<(GDIM * 1024 + 255) / 256, 256>>>(W);
    lstm_init<<<(BATCH * 1024 + 255) / 256, 256>>>();

    dim3 grid(32, 4);   // 128 CTAs, 1/SM, all co-resident
    lstm_persist<<<grid, 256, SMEM_DYN>>>(x, W, bias, out);
}

// round 16
// speedup vs baseline: 1.2820x; 1.0736x over previous
#include <cuda_runtime.h>
#include <cuda_bf16.h>
#include <math.h>
#include <stdint.h>

// LSTM scan: B=256, T=512, D=1, H=512. W:[513,2048] (i,j,f,o). out fp32 [B,T,H].
// bf16 HMMA, fp32 via 3-term split: ahi*whi + ahi*wlo + alo*whi.
// Round 16: round-15 frozen + fast-math epilogue (__expf/__fdividef sigmoid/tanh)
// to shorten the serial epilogue->barrier chain. Error budget checked: ~2e-5.

#define BATCH 256
#define TSTEPS 512
#define HDIM 512
#define GDIM 2048
#define A_OFF     131072            // W: 16 tiles x 8KB, then A ring 2 x 32KB
#define SMEM_DYN  196608
#define ZPITCH 66

__device__ __align__(16) __nv_bfloat16 g_Wp[GDIM * 1024];     // [p][whi(512)|wlo(512)]
__device__ __align__(16) __nv_bfloat16 g_A[2][BATCH * 1024];  // [b][hi(512)|lo(512)]
__device__ unsigned int g_bar[4];

__device__ __forceinline__ uint32_t cvta_s(const void* p) {
    return (uint32_t)__cvta_generic_to_shared(p);
}
__device__ __forceinline__ void cp16(uint32_t dst, const void* src) {
    asm volatile("cp.async.cg.shared.global [%0], [%1], 16;" :: "r"(dst), "l"(src));
}
#define CP_COMMIT() asm volatile("cp.async.commit_group;")
#define CP_WAIT0()  asm volatile("cp.async.wait_group 0;")

#define LDSM_X4(r0, r1, r2, r3, a)                                             \
    asm volatile("ldmatrix.sync.aligned.m8n8.x4.shared.b16 {%0,%1,%2,%3}, [%4];" \
                 : "=r"(r0), "=r"(r1), "=r"(r2), "=r"(r3) : "r"(a))

#define MMA16816(c, a0, a1, a2, a3, b0, b1)                                    \
    asm volatile("mma.sync.aligned.m16n8k16.row.col.f32.bf16.bf16.f32 "        \
                 "{%0,%1,%2,%3}, {%4,%5,%6,%7}, {%8,%9}, {%0,%1,%2,%3};"       \
                 : "+f"((c)[0]), "+f"((c)[1]), "+f"((c)[2]), "+f"((c)[3])      \
                 : "r"(a0), "r"(a1), "r"(a2), "r"(a3), "r"(b0), "r"(b1))

#define MMA_PASS(A, B)                                                          \
    _Pragma("unroll")                                                           \
    for (int kk = 0; kk < 2; kk++) {                                            \
        const uint32_t* a = (A) + kk * 8;                                       \
        const uint32_t* b = (B) + kk * 8;                                       \
        MMA16816(acc[0][0], a[0], a[1], a[2], a[3], b[0], b[1]);                \
        MMA16816(acc[0][1], a[0], a[1], a[2], a[3], b[2], b[3]);                \
        MMA16816(acc[0][2], a[0], a[1], a[2], a[3], b[4], b[5]);                \
        MMA16816(acc[0][3], a[0], a[1], a[2], a[3], b[6], b[7]);                \
        MMA16816(acc[1][0], a[4], a[5], a[6], a[7], b[0], b[1]);                \
        MMA16816(acc[1][1], a[4], a[5], a[6], a[7], b[2], b[3]);                \
        MMA16816(acc[1][2], a[4], a[5], a[6], a[7], b[4], b[5]);                \
        MMA16816(acc[1][3], a[4], a[5], a[6], a[7], b[6], b[7]);                \
    }

// fast sigmoid/tanh: MUFU.EX2 + MUFU.RCP path, exact saturation at +-inf.
__device__ __forceinline__ float fast_sig(float v) {
    return __fdividef(1.0f, 1.0f + __expf(-v));
}
__device__ __forceinline__ float fast_tanh(float v) {
    return __fdividef(2.0f, 1.0f + __expf(-2.0f * v)) - 1.0f;
}

// W'[p][k]: p = h*4+g -> gcol = g*512+h; k<512: Whi(k), k>=512: Wlo(k-512).
__global__ void conv_w(const float* __restrict__ W) {
    int idx = blockIdx.x * blockDim.x + threadIdx.x;
    if (idx >= GDIM * 1024) return;
    int p = idx >> 10;
    int k = idx & 1023;
    int g = p & 3, h = p >> 2;
    int kk = k & 511;
    float w = W[(size_t)(kk + 1) * GDIM + g * HDIM + h];
    __nv_bfloat16 hi = __float2bfloat16(w);
    g_Wp[idx] = (k >= 512) ? __float2bfloat16(w - __bfloat162float(hi)) : hi;
}

__global__ void lstm_init() {
    int i = blockIdx.x * blockDim.x + threadIdx.x;
    if (i < BATCH * 1024) {
        g_A[0][i] = __float2bfloat16(0.0f);
        g_A[1][i] = __float2bfloat16(0.0f);
    }
    if (i < 4) g_bar[i] = 0u;
}

// grid (32 nb, 4 mb) = 128 CTAs, 256 threads (8 warps), persistent over t.
__global__ void __launch_bounds__(256, 1) lstm_persist(
    const float* __restrict__ x,
    const float* __restrict__ W,
    const float* __restrict__ bias,
    float* __restrict__ out)
{
    extern __shared__ __align__(128) char dsmem[];
    __shared__ float s_w0[64], s_b[64];

    const int tid = threadIdx.x;
    const int wid = tid >> 5;
    const int lane = tid & 31;
    const int nb = blockIdx.x;
    const int mb = blockIdx.y;
    const int m_base = mb * 64;

    const uint32_t sbase = cvta_s(dsmem);
    const uint32_t abase = sbase + A_OFF;
    float* z0 = (float*)(dsmem + A_OFF);
    float* z1 = z0 + 64 * ZPITCH;

    const int ks = wid >> 2;
    const int w2 = wid & 3;
    const int warp_m = (w2 >> 1) * 32;
    const int warp_n = (w2 & 1) * 32;

    if (tid < 64) {
        int gcol = (tid & 3) * HDIM + nb * 16 + (tid >> 2);
        s_w0[tid] = W[gcol];
        s_b[tid] = bias[gcol];
    }

    const int lr = tid >> 3;
    const int lc16 = tid & 7;
    const uint32_t so0 = (uint32_t)(lr * 128 + ((lc16 ^ (lr & 7)) * 16));
    const uint32_t so1 = (uint32_t)((lr + 32) * 128 + ((lc16 ^ (lr & 7)) * 16));

    // ---- preload W slice into smem: 16 tiles (whi 0-7, wlo 8-15) ----
    #pragma unroll 1
    for (int j = 0; j < 16; j++) {
        int wo = ((j >= 8) ? 512 : 0) + (j & 7) * 64;
        cp16(sbase + j * 8192 + so0,
             &g_Wp[(size_t)(nb * 64 + lr) * 1024 + wo + lc16 * 8]);
        cp16(sbase + j * 8192 + so1,
             &g_Wp[(size_t)(nb * 64 + lr + 32) * 1024 + wo + lc16 * 8]);
    }
    CP_COMMIT();
    CP_WAIT0();
    __syncthreads();

    // ---- LDSM addressing ----
    const uint32_t a_row = warp_m + (lane & 15);
    const uint32_t b_row = warp_n + (lane & 7) + ((lane >> 4) << 3);
    const uint32_t a_sw = a_row & 7, b_sw = b_row & 7;
    const uint32_t a_c16base = ks * 4 + (lane >> 4);
    const uint32_t b_c16base = ks * 4 + ((lane >> 3) & 1);

    // ---- per-thread persistent cell state ----
    float creg[4] = {0.0f, 0.0f, 0.0f, 0.0f};

    #pragma unroll 1
    for (int t = 0; t < TSTEPS; t++) {
        const __nv_bfloat16* __restrict__ Ain = g_A[t & 1];
        __nv_bfloat16* __restrict__ Aout = g_A[(t + 1) & 1];

        // preload x for this step (independent of h; hides behind the GEMM)
        float xv[4];
        #pragma unroll
        for (int i = 0; i < 4; i++) {
            int b_row = m_base + ((i * 256 + tid) >> 4);
            xv[i] = x[b_row * TSTEPS + t];
        }

        // chunk i covers k in [128i, 128i+128): slot = 4 subtiles of 8KB
        // [hi_sub0 | hi_sub1 | lo_sub0 | lo_sub1]
        auto prefA = [&](int i) {
            uint32_t ab = abase + (i & 1) * 32768;
            const __nv_bfloat16* s0 = &Ain[(size_t)(m_base + lr) * 1024 + i * 128 + lc16 * 8];
            const __nv_bfloat16* s1 = &Ain[(size_t)(m_base + lr + 32) * 1024 + i * 128 + lc16 * 8];
            cp16(ab + so0, s0);                  // hi sub0
            cp16(ab + so1, s1);
            cp16(ab + 8192 + so0, s0 + 64);      // hi sub1
            cp16(ab + 8192 + so1, s1 + 64);
            cp16(ab + 16384 + so0, s0 + 512);    // lo sub0
            cp16(ab + 16384 + so1, s1 + 512);
            cp16(ab + 24576 + so0, s0 + 576);    // lo sub1
            cp16(ab + 24576 + so1, s1 + 576);
        };

        float acc[2][4][4] = {};

        prefA(0); CP_COMMIT();

        #pragma unroll 1
        for (int i = 0; i < 4; i++) {
            CP_WAIT0();          // my share of chunk i landed (<=1 group in flight)
            __syncthreads();     // publish chunk i; iter i-1 readers done
            if (i + 1 < 4) prefA(i + 1);   // slot (i+1)&1: readers were iter i-1
            CP_COMMIT();

            const uint32_t ab = abase + (i & 1) * 32768;
            #pragma unroll
            for (int sub = 0; sub < 2; sub++) {
                // W fragments for 64k-subchunk (2i+sub)
                uint32_t bh[16], bl[16];
                const uint32_t whb = sbase + (2 * i + sub) * 8192;
                const uint32_t wlb = sbase + (8 + 2 * i + sub) * 8192;
                #pragma unroll
                for (int kk = 0; kk < 2; kk++) {
                    uint32_t c16b = ((b_c16base + kk * 2) ^ b_sw) * 16;
                    uint32_t baddr = whb + b_row * 128 + c16b;
                    LDSM_X4(bh[kk*8+0], bh[kk*8+1], bh[kk*8+2], bh[kk*8+3], baddr);
                    LDSM_X4(bh[kk*8+4], bh[kk*8+5], bh[kk*8+6], bh[kk*8+7], baddr + 16 * 128);
                    uint32_t baddr2 = wlb + b_row * 128 + c16b;
                    LDSM_X4(bl[kk*8+0], bl[kk*8+1], bl[kk*8+2], bl[kk*8+3], baddr2);
                    LDSM_X4(bl[kk*8+4], bl[kk*8+5], bl[kk*8+6], bl[kk*8+7], baddr2 + 16 * 128);
                }

                uint32_t ah[16], al[16];
                const uint32_t ahb = ab + sub * 8192;           // hi subtile
                const uint32_t alb = ab + 16384 + sub * 8192;   // lo subtile
                #pragma unroll
                for (int kk = 0; kk < 2; kk++) {
                    uint32_t c16a = ((a_c16base + kk * 2) ^ a_sw) * 16;
                    uint32_t aaddr = ahb + a_row * 128 + c16a;
                    LDSM_X4(ah[kk*8+0], ah[kk*8+1], ah[kk*8+2], ah[kk*8+3], aaddr);
                    LDSM_X4(ah[kk*8+4], ah[kk*8+5], ah[kk*8+6], ah[kk*8+7], aaddr + 16 * 128);
                    uint32_t aaddr2 = alb + a_row * 128 + c16a;
                    LDSM_X4(al[kk*8+0], al[kk*8+1], al[kk*8+2], al[kk*8+3], aaddr2);
                    LDSM_X4(al[kk*8+4], al[kk*8+5], al[kk*8+6], al[kk*8+7], aaddr2 + 16 * 128);
                }

                MMA_PASS(ah, bh);    // a_hi * w_hi
                MMA_PASS(ah, bl);    // a_hi * w_lo
                MMA_PASS(al, bh);    // a_lo * w_hi
            }
        }
        __syncthreads();     // z aliases slot 0 + head of slot 1 (iter-3 readers)

        // ---- z stage (dual accumulators per k-split) ----
        float* zw = ks ? z1 : z0;
        #pragma unroll
        for (int mf = 0; mf < 2; mf++)
            #pragma unroll
            for (int nf = 0; nf < 4; nf++) {
                int row = warp_m + mf * 16 + (lane >> 2);
                int col = warp_n + nf * 8 + (lane & 3) * 2;
                *(float2*)&zw[row * ZPITCH + col] =
                    make_float2(acc[mf][nf][0], acc[mf][nf][1]);
                *(float2*)&zw[(row + 8) * ZPITCH + col] =
                    make_float2(acc[mf][nf][2], acc[mf][nf][3]);
            }
        __syncthreads();

        // ---- gate fusion: fast-math transcendentals; out stores deferred ----
        float hnv[4];
        int orow[4], ocol[4];
        #pragma unroll
        for (int i = 0; i < 4; i++) {
            int o = i * 256 + tid;
            int r = o >> 4;
            int h = o & 15;
            int b_row = m_base + r;
            int h_col = nb * 16 + h;
            orow[i] = b_row; ocol[i] = h_col;

            const float* za = &z0[r * ZPITCH + h * 4];
            const float* zb = &z1[r * ZPITCH + h * 4];

            float zi = za[0] + zb[0] + fmaf(xv[i], s_w0[h * 4 + 0], s_b[h * 4 + 0]);
            float zj = za[1] + zb[1] + fmaf(xv[i], s_w0[h * 4 + 1], s_b[h * 4 + 1]);
            float zf = za[2] + zb[2] + fmaf(xv[i], s_w0[h * 4 + 2], s_b[h * 4 + 2]);
            float zo = za[3] + zb[3] + fmaf(xv[i], s_w0[h * 4 + 3], s_b[h * 4 + 3]);

            float fg = fast_sig(zf + 1.0f);
            float ig = fast_sig(zi);
            float og = fast_sig(zo);
            float cn = creg[i] * fg + ig * fast_tanh(zj);
            float hn = fast_tanh(cn) * og;
            creg[i] = cn;
            hnv[i] = hn;

            __nv_bfloat16 hi = __float2bfloat16(hn);
            __nv_bfloat16 lo = __float2bfloat16(hn - __bfloat162float(hi));
            Aout[(size_t)b_row * 1024 + h_col] = hi;
            Aout[(size_t)b_row * 1024 + 512 + h_col] = lo;
        }

        // ---- arrive early: Aout published, then overlap out stores ----
        const int last = (t == TSTEPS - 1);
        if (!last) {
            __syncthreads();              // all threads' Aout stores done
            if (tid == 0) {
                __threadfence();          // tid-0 only: release Aout gpu-wide
                asm volatile("red.release.gpu.global.add.u32 [%0], %1;"
                             :: "l"(&g_bar[mb]), "r"(1u) : "memory");
            }
        }

        // ---- streaming out stores (write-once), overlap other CTAs' work ----
        #pragma unroll
        for (int i = 0; i < 4; i++) {
            __stcs(&out[(size_t)orow[i] * (TSTEPS * HDIM) + (size_t)t * HDIM + ocol[i]],
                   hnv[i]);
        }

        if (!last) {
            if (tid == 0) {
                unsigned int target = 32u * (unsigned)(t + 1);
                unsigned int v;
                do {
                    asm volatile("ld.acquire.gpu.global.u32 %0, [%1];"
                                 : "=r"(v) : "l"(&g_bar[mb]) : "memory");
                } while (v < target);
            }
            __syncthreads();
        }
    }
}

extern "C" void kernel_launch(void* const* d_in, const int* in_sizes, int n_in,
                              void* d_out, int out_size) {
    const float* x    = (const float*)d_in[0];
    const float* W    = (const float*)d_in[1];
    const float* bias = (const float*)d_in[2];
    float* out = (float*)d_out;
    (void)in_sizes; (void)n_in; (void)out_size;

    cudaFuncSetAttribute(lstm_persist,
                         cudaFuncAttributeMaxDynamicSharedMemorySize, SMEM_DYN);

    conv_w<<<(GDIM * 1024 + 255) / 256, 256>>>(W);
    lstm_init<<<(BATCH * 1024 + 255) / 256, 256>>>();

    dim3 grid(32, 4);   // 128 CTAs, 1/SM, all co-resident
    lstm_persist<<<grid, 256, SMEM_DYN>>>(x, W, bias, out);
}

// round 17
// speedup vs baseline: 1.3513x; 1.0541x over previous
#include <cuda_runtime.h>
#include <cuda_bf16.h>
#include <math.h>
#include <stdint.h>

// LSTM scan: B=256, T=512, D=1, H=512. W:[513,2048] (i,j,f,o). out fp32 [B,T,H].
// bf16 HMMA, fp32 via 3-term split: ahi*whi + ahi*wlo + alo*whi.
// Round 17: round-16 frozen + (a) z in dedicated smem (drops ring-guard sync),
// (b) sub-0 W-LDSM hoisted above the cp.async wait, (c) x-preload after prefA(0).

#define BATCH 256
#define TSTEPS 512
#define HDIM 512
#define GDIM 2048
#define A_OFF     131072            // W: 16x8KB | A ring: 2x32KB | z: 33KB
#define Z_OFF     196608
#define SMEM_DYN  230400
#define ZPITCH 66

__device__ __align__(16) __nv_bfloat16 g_Wp[GDIM * 1024];     // [p][whi(512)|wlo(512)]
__device__ __align__(16) __nv_bfloat16 g_A[2][BATCH * 1024];  // [b][hi(512)|lo(512)]
__device__ unsigned int g_bar[4];

__device__ __forceinline__ uint32_t cvta_s(const void* p) {
    return (uint32_t)__cvta_generic_to_shared(p);
}
__device__ __forceinline__ void cp16(uint32_t dst, const void* src) {
    asm volatile("cp.async.cg.shared.global [%0], [%1], 16;" :: "r"(dst), "l"(src));
}
#define CP_COMMIT() asm volatile("cp.async.commit_group;")
#define CP_WAIT0()  asm volatile("cp.async.wait_group 0;")

#define LDSM_X4(r0, r1, r2, r3, a)                                             \
    asm volatile("ldmatrix.sync.aligned.m8n8.x4.shared.b16 {%0,%1,%2,%3}, [%4];" \
                 : "=r"(r0), "=r"(r1), "=r"(r2), "=r"(r3) : "r"(a))

#define MMA16816(c, a0, a1, a2, a3, b0, b1)                                    \
    asm volatile("mma.sync.aligned.m16n8k16.row.col.f32.bf16.bf16.f32 "        \
                 "{%0,%1,%2,%3}, {%4,%5,%6,%7}, {%8,%9}, {%0,%1,%2,%3};"       \
                 : "+f"((c)[0]), "+f"((c)[1]), "+f"((c)[2]), "+f"((c)[3])      \
                 : "r"(a0), "r"(a1), "r"(a2), "r"(a3), "r"(b0), "r"(b1))

#define MMA_PASS(A, B)                                                          \
    _Pragma("unroll")                                                           \
    for (int kk = 0; kk < 2; kk++) {                                            \
        const uint32_t* a = (A) + kk * 8;                                       \
        const uint32_t* b = (B) + kk * 8;                                       \
        MMA16816(acc[0][0], a[0], a[1], a[2], a[3], b[0], b[1]);                \
        MMA16816(acc[0][1], a[0], a[1], a[2], a[3], b[2], b[3]);                \
        MMA16816(acc[0][2], a[0], a[1], a[2], a[3], b[4], b[5]);                \
        MMA16816(acc[0][3], a[0], a[1], a[2], a[3], b[6], b[7]);                \
        MMA16816(acc[1][0], a[4], a[5], a[6], a[7], b[0], b[1]);                \
        MMA16816(acc[1][1], a[4], a[5], a[6], a[7], b[2], b[3]);                \
        MMA16816(acc[1][2], a[4], a[5], a[6], a[7], b[4], b[5]);                \
        MMA16816(acc[1][3], a[4], a[5], a[6], a[7], b[6], b[7]);                \
    }

// W-fragment loader for 64k-subchunk `sc` (0..7): fills bh[16], bl[16]
#define LOAD_W_FRAGS(sc, bh, bl)                                                \
    {                                                                           \
        const uint32_t whb = sbase + (sc) * 8192;                               \
        const uint32_t wlb = sbase + (8 + (sc)) * 8192;                         \
        _Pragma("unroll")                                                       \
        for (int kk = 0; kk < 2; kk++) {                                        \
            uint32_t c16b = ((b_c16base + kk * 2) ^ b_sw) * 16;                 \
            uint32_t baddr = whb + b_row * 128 + c16b;                          \
            LDSM_X4((bh)[kk*8+0], (bh)[kk*8+1], (bh)[kk*8+2], (bh)[kk*8+3], baddr); \
            LDSM_X4((bh)[kk*8+4], (bh)[kk*8+5], (bh)[kk*8+6], (bh)[kk*8+7], baddr + 16 * 128); \
            uint32_t baddr2 = wlb + b_row * 128 + c16b;                         \
            LDSM_X4((bl)[kk*8+0], (bl)[kk*8+1], (bl)[kk*8+2], (bl)[kk*8+3], baddr2); \
            LDSM_X4((bl)[kk*8+4], (bl)[kk*8+5], (bl)[kk*8+6], (bl)[kk*8+7], baddr2 + 16 * 128); \
        }                                                                       \
    }

// A-fragment loader: hi subtile at ahb, lo subtile at alb
#define LOAD_A_FRAGS(ahb, alb, ah, al)                                          \
    {                                                                           \
        _Pragma("unroll")                                                       \
        for (int kk = 0; kk < 2; kk++) {                                        \
            uint32_t c16a = ((a_c16base + kk * 2) ^ a_sw) * 16;                 \
            uint32_t aaddr = (ahb) + a_row * 128 + c16a;                        \
            LDSM_X4((ah)[kk*8+0], (ah)[kk*8+1], (ah)[kk*8+2], (ah)[kk*8+3], aaddr); \
            LDSM_X4((ah)[kk*8+4], (ah)[kk*8+5], (ah)[kk*8+6], (ah)[kk*8+7], aaddr + 16 * 128); \
            uint32_t aaddr2 = (alb) + a_row * 128 + c16a;                       \
            LDSM_X4((al)[kk*8+0], (al)[kk*8+1], (al)[kk*8+2], (al)[kk*8+3], aaddr2); \
            LDSM_X4((al)[kk*8+4], (al)[kk*8+5], (al)[kk*8+6], (al)[kk*8+7], aaddr2 + 16 * 128); \
        }                                                                       \
    }

// fast sigmoid/tanh: MUFU.EX2 + MUFU.RCP path, exact saturation at +-inf.
__device__ __forceinline__ float fast_sig(float v) {
    return __fdividef(1.0f, 1.0f + __expf(-v));
}
__device__ __forceinline__ float fast_tanh(float v) {
    return __fdividef(2.0f, 1.0f + __expf(-2.0f * v)) - 1.0f;
}

// W'[p][k]: p = h*4+g -> gcol = g*512+h; k<512: Whi(k), k>=512: Wlo(k-512).
__global__ void conv_w(const float* __restrict__ W) {
    int idx = blockIdx.x * blockDim.x + threadIdx.x;
    if (idx >= GDIM * 1024) return;
    int p = idx >> 10;
    int k = idx & 1023;
    int g = p & 3, h = p >> 2;
    int kk = k & 511;
    float w = W[(size_t)(kk + 1) * GDIM + g * HDIM + h];
    __nv_bfloat16 hi = __float2bfloat16(w);
    g_Wp[idx] = (k >= 512) ? __float2bfloat16(w - __bfloat162float(hi)) : hi;
}

__global__ void lstm_init() {
    int i = blockIdx.x * blockDim.x + threadIdx.x;
    if (i < BATCH * 1024) {
        g_A[0][i] = __float2bfloat16(0.0f);
        g_A[1][i] = __float2bfloat16(0.0f);
    }
    if (i < 4) g_bar[i] = 0u;
}

// grid (32 nb, 4 mb) = 128 CTAs, 256 threads (8 warps), persistent over t.
__global__ void __launch_bounds__(256, 1) lstm_persist(
    const float* __restrict__ x,
    const float* __restrict__ W,
    const float* __restrict__ bias,
    float* __restrict__ out)
{
    extern __shared__ __align__(128) char dsmem[];
    __shared__ float s_w0[64], s_b[64];

    const int tid = threadIdx.x;
    const int wid = tid >> 5;
    const int lane = tid & 31;
    const int nb = blockIdx.x;
    const int mb = blockIdx.y;
    const int m_base = mb * 64;

    const uint32_t sbase = cvta_s(dsmem);
    const uint32_t abase = sbase + A_OFF;
    float* z0 = (float*)(dsmem + Z_OFF);          // dedicated: no ring alias
    float* z1 = z0 + 64 * ZPITCH;

    const int ks = wid >> 2;
    const int w2 = wid & 3;
    const int warp_m = (w2 >> 1) * 32;
    const int warp_n = (w2 & 1) * 32;

    if (tid < 64) {
        int gcol = (tid & 3) * HDIM + nb * 16 + (tid >> 2);
        s_w0[tid] = W[gcol];
        s_b[tid] = bias[gcol];
    }

    const int lr = tid >> 3;
    const int lc16 = tid & 7;
    const uint32_t so0 = (uint32_t)(lr * 128 + ((lc16 ^ (lr & 7)) * 16));
    const uint32_t so1 = (uint32_t)((lr + 32) * 128 + ((lc16 ^ (lr & 7)) * 16));

    // ---- preload W slice into smem: 16 tiles (whi 0-7, wlo 8-15) ----
    #pragma unroll 1
    for (int j = 0; j < 16; j++) {
        int wo = ((j >= 8) ? 512 : 0) + (j & 7) * 64;
        cp16(sbase + j * 8192 + so0,
             &g_Wp[(size_t)(nb * 64 + lr) * 1024 + wo + lc16 * 8]);
        cp16(sbase + j * 8192 + so1,
             &g_Wp[(size_t)(nb * 64 + lr + 32) * 1024 + wo + lc16 * 8]);
    }
    CP_COMMIT();
    CP_WAIT0();
    __syncthreads();

    // ---- LDSM addressing ----
    const uint32_t a_row = warp_m + (lane & 15);
    const uint32_t b_row = warp_n + (lane & 7) + ((lane >> 4) << 3);
    const uint32_t a_sw = a_row & 7, b_sw = b_row & 7;
    const uint32_t a_c16base = ks * 4 + (lane >> 4);
    const uint32_t b_c16base = ks * 4 + ((lane >> 3) & 1);

    // ---- per-thread persistent cell state ----
    float creg[4] = {0.0f, 0.0f, 0.0f, 0.0f};

    #pragma unroll 1
    for (int t = 0; t < TSTEPS; t++) {
        const __nv_bfloat16* __restrict__ Ain = g_A[t & 1];
        __nv_bfloat16* __restrict__ Aout = g_A[(t + 1) & 1];

        // chunk i covers k in [128i, 128i+128): slot = 4 subtiles of 8KB
        // [hi_sub0 | hi_sub1 | lo_sub0 | lo_sub1]
        auto prefA = [&](int i) {
            uint32_t ab = abase + (i & 1) * 32768;
            const __nv_bfloat16* s0 = &Ain[(size_t)(m_base + lr) * 1024 + i * 128 + lc16 * 8];
            const __nv_bfloat16* s1 = &Ain[(size_t)(m_base + lr + 32) * 1024 + i * 128 + lc16 * 8];
            cp16(ab + so0, s0);                  // hi sub0
            cp16(ab + so1, s1);
            cp16(ab + 8192 + so0, s0 + 64);      // hi sub1
            cp16(ab + 8192 + so1, s1 + 64);
            cp16(ab + 16384 + so0, s0 + 512);    // lo sub0
            cp16(ab + 16384 + so1, s1 + 512);
            cp16(ab + 24576 + so0, s0 + 576);    // lo sub1
            cp16(ab + 24576 + so1, s1 + 576);
        };

        float acc[2][4][4] = {};

        prefA(0); CP_COMMIT();   // first memory op after the barrier

        // x preload after the cp.asyncs (independent of h; hides behind GEMM)
        float xv[4];
        #pragma unroll
        for (int i = 0; i < 4; i++) {
            int b_row = m_base + ((i * 256 + tid) >> 4);
            xv[i] = x[b_row * TSTEPS + t];
        }

        #pragma unroll 1
        for (int i = 0; i < 4; i++) {
            // sub-0 W fragments BEFORE the wait: static tiles, fill the shadow
            uint32_t bh[16], bl[16];
            LOAD_W_FRAGS(2 * i, bh, bl);

            CP_WAIT0();          // my share of chunk i landed (<=1 group in flight)
            __syncthreads();     // publish chunk i; iter i-1 readers done
            if (i + 1 < 4) prefA(i + 1);   // slot (i+1)&1: readers were iter i-1
            CP_COMMIT();

            const uint32_t ab = abase + (i & 1) * 32768;

            // ---- sub 0 ----
            {
                uint32_t ah[16], al[16];
                LOAD_A_FRAGS(ab, ab + 16384, ah, al);
                MMA_PASS(ah, bh);    // a_hi * w_hi
                MMA_PASS(ah, bl);    // a_hi * w_lo
                MMA_PASS(al, bh);    // a_lo * w_hi
            }
            // ---- sub 1 ----
            {
                LOAD_W_FRAGS(2 * i + 1, bh, bl);
                uint32_t ah[16], al[16];
                LOAD_A_FRAGS(ab + 8192, ab + 24576, ah, al);
                MMA_PASS(ah, bh);
                MMA_PASS(ah, bl);
                MMA_PASS(al, bh);
            }
        }

        // ---- z stage: dedicated smem, no ring-guard sync needed ----
        float* zw = ks ? z1 : z0;
        #pragma unroll
        for (int mf = 0; mf < 2; mf++)
            #pragma unroll
            for (int nf = 0; nf < 4; nf++) {
                int row = warp_m + mf * 16 + (lane >> 2);
                int col = warp_n + nf * 8 + (lane & 3) * 2;
                *(float2*)&zw[row * ZPITCH + col] =
                    make_float2(acc[mf][nf][0], acc[mf][nf][1]);
                *(float2*)&zw[(row + 8) * ZPITCH + col] =
                    make_float2(acc[mf][nf][2], acc[mf][nf][3]);
            }
        __syncthreads();

        // ---- gate fusion: fast-math transcendentals; out stores deferred ----
        float hnv[4];
        int orow[4], ocol[4];
        #pragma unroll
        for (int i = 0; i < 4; i++) {
            int o = i * 256 + tid;
            int r = o >> 4;
            int h = o & 15;
            int b_row = m_base + r;
            int h_col = nb * 16 + h;
            orow[i] = b_row; ocol[i] = h_col;

            const float* za = &z0[r * ZPITCH + h * 4];
            const float* zb = &z1[r * ZPITCH + h * 4];

            float zi = za[0] + zb[0] + fmaf(xv[i], s_w0[h * 4 + 0], s_b[h * 4 + 0]);
            float zj = za[1] + zb[1] + fmaf(xv[i], s_w0[h * 4 + 1], s_b[h * 4 + 1]);
            float zf = za[2] + zb[2] + fmaf(xv[i], s_w0[h * 4 + 2], s_b[h * 4 + 2]);
            float zo = za[3] + zb[3] + fmaf(xv[i], s_w0[h * 4 + 3], s_b[h * 4 + 3]);

            float fg = fast_sig(zf + 1.0f);
            float ig = fast_sig(zi);
            float og = fast_sig(zo);
            float cn = creg[i] * fg + ig * fast_tanh(zj);
            float hn = fast_tanh(cn) * og;
            creg[i] = cn;
            hnv[i] = hn;

            __nv_bfloat16 hi = __float2bfloat16(hn);
            __nv_bfloat16 lo = __float2bfloat16(hn - __bfloat162float(hi));
            Aout[(size_t)b_row * 1024 + h_col] = hi;
            Aout[(size_t)b_row * 1024 + 512 + h_col] = lo;
        }

        // ---- arrive early: Aout published, then overlap out stores ----
        const int last = (t == TSTEPS - 1);
        if (!last) {
            __syncthreads();              // all threads' Aout stores done
            if (tid == 0) {
                __threadfence();          // tid-0 only: release Aout gpu-wide
                asm volatile("red.release.gpu.global.add.u32 [%0], %1;"
                             :: "l"(&g_bar[mb]), "r"(1u) : "memory");
            }
        }

        // ---- streaming out stores (write-once), overlap other CTAs' work ----
        #pragma unroll
        for (int i = 0; i < 4; i++) {
            __stcs(&out[(size_t)orow[i] * (TSTEPS * HDIM) + (size_t)t * HDIM + ocol[i]],
                   hnv[i]);
        }

        if (!last) {
            if (tid == 0) {
                unsigned int target = 32u * (unsigned)(t + 1);
                unsigned int v;
                do {
                    asm volatile("ld.acquire.gpu.global.u32 %0, [%1];"
                                 : "=r"(v) : "l"(&g_bar[mb]) : "memory");
                } while (v < target);
            }
            __syncthreads();      // also orders step-t z reads before step-t+1 writes
        }
    }
}

extern "C" void kernel_launch(void* const* d_in, const int* in_sizes, int n_in,
                              void* d_out, int out_size) {
    const float* x    = (const float*)d_in[0];
    const float* W    = (const float*)d_in[1];
    const float* bias = (const float*)d_in[2];
    float* out = (float*)d_out;
    (void)in_sizes; (void)n_in; (void)out_size;

    cudaFuncSetAttribute(lstm_persist,
                         cudaFuncAttributeMaxDynamicSharedMemorySize, SMEM_DYN);

    conv_w<<<(GDIM * 1024 + 255) / 256, 256>>>(W);
    lstm_init<<<(BATCH * 1024 + 255) / 256, 256>>>();

    dim3 grid(32, 4);   // 128 CTAs, 1/SM, all co-resident
    lstm_persist<<<grid, 256, SMEM_DYN>>>(x, W, bias, out);
}